// round 9
// baseline (speedup 1.0000x reference)
#include <cuda_runtime.h>
#include <cstdint>

// ---------------------------------------------------------------------------
// ST-LSTM persistent kernel, fp32 f32x2. Round 8:
//  - per-warp DATAFLOW sync replaces the full grid barrier: warp ks waits only
//    on its 16 producer CTAs (ks<8: h[s-1] slice; ks>=8: h[s-25], ~free)
//  - flag = steps published per CTA; release = fence(gate stores) -> sync -> st
//  - h-GEMM software-pipelined 2 block-pairs deep; h stores via st.cg
//  - 3-LDS/k-row weight layout (WSTR=24); single-stage 16-row reduce
// 128 CTAs x 512 thr. CTA owns 4 h-cols (20 z-cols), full K=1280.
// ---------------------------------------------------------------------------

#define NCTA 128
#define NTHR 512

constexpr int Bb = 64, Ii = 256, Hh = 512;
constexpr int G5H   = 2560;
constexpr int STEPS = 1600;
constexpr int HB    = Hh * Bb;     // 32768
constexpr int XB    = Ii * Bb;     // 16384
constexpr int BH    = Bb * Hh;
constexpr int NPC   = 20;          // z-cols per CTA
constexpr int KSL   = 16;          // k-slices
constexpr int RS    = 1296;        // reduce row stride (floats)
constexpr int WSTR  = 24;          // W_s row stride; halves at +0 / +12

constexpr int W_OFF = 0;                    // 1280*24 = 30720
constexpr int R_OFF = 30720;                // 16*1296 = 20736
constexpr int C_OFF = R_OFF + KSL * RS;     // 25*256  = 6400
constexpr int SM_FLOATS  = C_OFF + 25 * 256;
constexpr int SMEM_BYTES = SM_FLOATS * 4;   // 231,424 B

// --------------------------- device scratch --------------------------------
__device__ float    g_xT[(size_t)STEPS * XB];  // x transposed [tj][i][b]
__device__ float    g_hT[32 * HB];             // h ring [slot][n][b]
__device__ unsigned g_flags[NCTA * 8];         // per-CTA published-step counters
__device__ unsigned g_cnt = 0;                 // init barrier (one-shot, self-reset)
__device__ unsigned g_gen = 0;

// --------------------------- helpers ---------------------------------------
__device__ __forceinline__ void init_barrier() {
    __syncthreads();
    if (threadIdx.x == 0) {
        unsigned gen = *(volatile unsigned*)&g_gen;
        __threadfence();
        unsigned rank = atomicAdd(&g_cnt, 1u);
        if (rank == NCTA - 1) {
            g_cnt = 0;
            __threadfence();
            *(volatile unsigned*)&g_gen = gen + 1u;
        } else {
            while (*(volatile unsigned*)&g_gen == gen) { __nanosleep(64); }
        }
        __threadfence();
    }
    __syncthreads();
}

// warp-level producer wait: lanes 0..15 poll 16 flags until >= target
__device__ __forceinline__ void warp_wait(int prodbase, int lane, int target) {
    if (target > 0) {
        if (lane < 16) {
            const unsigned* p = &g_flags[(prodbase + lane) * 8];
            unsigned v;
            asm volatile("ld.global.cg.u32 %0, [%1];" : "=r"(v) : "l"(p));
            while ((int)v < target) {
                __nanosleep(32);
                asm volatile("ld.global.cg.u32 %0, [%1];" : "=r"(v) : "l"(p));
            }
        }
        __syncwarp();
        __threadfence();   // acquire: order flag read before h loads
    }
}

__device__ __forceinline__ float fexp(float x) {
    float r;
    asm("ex2.approx.f32 %0, %1;" : "=f"(r) : "f"(x * 1.4426950408889634f));
    return r;
}
__device__ __forceinline__ float frcp(float x) {
    float r;
    asm("rcp.approx.f32 %0, %1;" : "=f"(r) : "f"(x));
    return r;
}
__device__ __forceinline__ float fsig(float x)  { return frcp(1.0f + fexp(-x)); }
__device__ __forceinline__ float ftanh(float x) { return 1.0f - 2.0f * frcp(1.0f + fexp(2.0f * x)); }

// --------------------------- kernel ----------------------------------------
__global__ void __launch_bounds__(NTHR, 1)
stlstm_kernel(const float* __restrict__ x,
              const float* __restrict__ Wx,
              const float* __restrict__ Whs,
              const float* __restrict__ Wht,
              const float* __restrict__ bias,
              float* __restrict__ out)
{
    extern __shared__ float sm[];
    float* W_s = sm + W_OFF;    // [1280][24]: local cols 0-9 at +0, 10-19 at +12
    float* red = sm + R_OFF;
    float* c_s = sm + C_OFF;

    const int t   = threadIdx.x;
    const int cta = blockIdx.x;
    const int nt  = cta;

    // -------- pre-barrier init: flags, x transpose, ring zero, weights ------
    if (t == 0) *(volatile unsigned*)&g_flags[cta * 8] = 0u;
    {
        float* tmp = red;                      // 20736 floats >= 64*257
        for (int tj = cta; tj < STEPS; tj += NCTA) {
            const float* xsrc = x + (size_t)tj * (Bb * Ii);
            for (int idx = t; idx < Bb * Ii; idx += NTHR) {
                int bb = idx >> 8, ii = idx & 255;
                tmp[bb * 257 + ii] = xsrc[idx];
            }
            __syncthreads();
            float* xdst = g_xT + (size_t)tj * XB;
            for (int idx = t; idx < Bb * Ii; idx += NTHR) {
                int ii = idx >> 6, bb = idx & 63;
                xdst[idx] = tmp[bb * 257 + ii];
            }
            __syncthreads();
        }
    }
    {   // zero h-ring slots 7..31 (all early reads land there)
        float* z = g_hT + 7 * HB;
        for (int idx = cta * NTHR + t; idx < 25 * HB; idx += NCTA * NTHR) z[idx] = 0.0f;
    }
    for (int idx = t; idx < 25 * 256; idx += NTHR) c_s[idx] = 0.0f;

    // weights: local col c in [0,20); SMEM slot c<10 ? c : c+2
    for (int idx = t; idx < 1280 * NPC; idx += NTHR) {
        int k = idx / NPC, c = idx % NPC;
        int g = c >> 2, hc = c & 3;
        int col = g * Hh + nt * 4 + hc;
        float w;
        if (k < Hh)            w = Whs[(size_t)k * G5H + col];
        else if (k < 2 * Hh)   w = Wht[(size_t)(k - Hh) * G5H + col];
        else                   w = Wx [(size_t)(k - 2 * Hh) * G5H + col];
        W_s[k * WSTR + (c < 10 ? c : c + 2)] = w;
    }

    float ba[5];
    {
        int hc = t & 3;
        #pragma unroll
        for (int g = 0; g < 5; ++g) ba[g] = bias[g * Hh + nt * 4 + hc];
    }

    init_barrier();   // x ready, rings zeroed, flags zeroed everywhere

    // GEMM mapping: thread = (ng, mg, ks); ks warp-uniform.
    const int ng   = t & 1;
    const int mg   = (t >> 1) & 15;
    const int ks   = t >> 5;
    const int lane = t & 31;
    const int b_lo = mg * 4;
    const int ng12 = ng * 12;            // W_s half offset (floats)
    const int ng10 = ng * 10;            // red half offset
    const int khW  = ks * 64;            // W row base, h part
    const int kxW  = 1024 + ks * 16;     // W row base, x part

    // producer set for this warp's h slice
    const int prodbase = ((ks < 8) ? ks : (ks - 8)) * 16;
    const int tgt_off  = (ks < 8) ? 0 : 24;   // wait target = step - tgt_off

    const int bg  = t >> 2;              // gate phase (t < 256)
    const int hcg = t & 3;

    unsigned long long acc[4][5];
    float4 bufA[4], bufB[4];

#define ZERO_ACC()                                                            \
    {  _Pragma("unroll")                                                      \
       for (int i = 0; i < 4; ++i)                                            \
           _Pragma("unroll")                                                  \
           for (int g = 0; g < 5; ++g) acc[i][g] = 0ull; }

#define LOADBLK(BUF, PA, BLK)                                                 \
    {  _Pragma("unroll")                                                      \
       for (int u = 0; u < 4; ++u)                                            \
           BUF[u] = __ldcg((const float4*)((PA) + ((BLK) * 4 + u) * 64));     \
    }

#define FMABLK(BUF, KWB, BLK)                                                 \
    {  _Pragma("unroll")                                                      \
       for (int u = 0; u < 4; ++u) {                                          \
           const float* wr = W_s + ((KWB) + (BLK) * 4 + u) * WSTR + ng12;     \
           ulonglong2 wa = *(const ulonglong2*)(wr);                          \
           ulonglong2 wb = *(const ulonglong2*)(wr + 4);                      \
           unsigned long long w4 = *(const unsigned long long*)(wr + 8);      \
           float av[4] = {BUF[u].x, BUF[u].y, BUF[u].z, BUF[u].w};            \
           _Pragma("unroll")                                                  \
           for (int i = 0; i < 4; ++i) {                                      \
               unsigned long long aa;                                         \
               asm("mov.b64 %0, {%1, %1};" : "=l"(aa) : "f"(av[i]));          \
               asm("fma.rn.f32x2 %0, %1, %2, %0;" : "+l"(acc[i][0]) : "l"(aa), "l"(wa.x)); \
               asm("fma.rn.f32x2 %0, %1, %2, %0;" : "+l"(acc[i][1]) : "l"(aa), "l"(wa.y)); \
               asm("fma.rn.f32x2 %0, %1, %2, %0;" : "+l"(acc[i][2]) : "l"(aa), "l"(wb.x)); \
               asm("fma.rn.f32x2 %0, %1, %2, %0;" : "+l"(acc[i][3]) : "l"(aa), "l"(wb.y)); \
               asm("fma.rn.f32x2 %0, %1, %2, %0;" : "+l"(acc[i][4]) : "l"(aa), "l"(w4)); \
           } } }

    // full x-part (16 rows, 4 blocks) — no cross-CTA dependency
#define XGEMM(S)                                                              \
    {  const float* pX = g_xT + (size_t)(S) * XB + (ks * 16) * 64 + b_lo;     \
       LOADBLK(bufA, pX, 0)                                                   \
       LOADBLK(bufB, pX, 1)                                                   \
       FMABLK(bufA, kxW, 0)                                                   \
       LOADBLK(bufA, pX, 2)                                                   \
       FMABLK(bufB, kxW, 1)                                                   \
       LOADBLK(bufB, pX, 3)                                                   \
       FMABLK(bufA, kxW, 2)                                                   \
       FMABLK(bufB, kxW, 3) }

    // prologue: x-part of step 0
    ZERO_ACC()
    XGEMM(0)

    // ---------------- main sequential loop ----------------------------------
    for (int step = 0; step < STEPS; ++step) {

        // ---- per-warp dataflow wait on this warp's 16 producers ----
        warp_wait(prodbase, lane, step - tgt_off);

        // ---- h-part GEMM: 16 blocks, pipelined 2 pairs deep ----
        {
            const float* h1  = g_hT + ((step - 1)  & 31) * HB;
            const float* h25 = g_hT + ((step - 25) & 31) * HB;
            const float* pH  = ((ks < 8) ? (h1 + khW * 64)
                                         : (h25 + (khW - 512) * 64)) + b_lo;
            LOADBLK(bufA, pH, 0)
            LOADBLK(bufB, pH, 1)
            #pragma unroll 1
            for (int blk = 0; blk < 16; blk += 2) {
                FMABLK(bufA, khW, blk)
                if (blk + 2 < 16) LOADBLK(bufA, pH, blk + 2)
                FMABLK(bufB, khW, blk + 1)
                if (blk + 3 < 16) LOADBLK(bufB, pH, blk + 3)
            }
        }

        __syncthreads();   // red buffer free (previous gate phase done)

        // ---- store partials: thread's 10 contiguous local cols ----
        {
            float* rrow = red + ks * RS + ng10;
            #pragma unroll
            for (int i = 0; i < 4; ++i) {
                float* rb = rrow + (b_lo + i) * NPC;
                #pragma unroll
                for (int p = 0; p < 5; ++p)
                    *(float2*)(rb + 2 * p) = *(float2*)&acc[i][p];
            }
        }
        __syncthreads();

        // ---- reduce 16 k-slices + gates (threads 0..255), fence stores ----
        if (t < 256) {
            float z[5];
            #pragma unroll
            for (int g = 0; g < 5; ++g) {
                float s = ba[g];
                const float* rp = red + bg * NPC + g * 4 + hcg;
                #pragma unroll
                for (int q = 0; q < KSL; ++q) s += rp[q * RS];
                z[g] = s;
            }
            float cs = c_s[((step + 24) % 25) * 256 + t];
            float ct = c_s[(step % 25) * 256 + t];
            float cc = fsig(z[0]) * ftanh(z[3]) + fsig(z[1]) * cs + fsig(z[2]) * ct;
            float hv = fsig(z[4]) * ftanh(cc);
            c_s[(step % 25) * 256 + t] = cc;

            int n = nt * 4 + hcg;
            __stcg(&g_hT[(step & 31) * HB + n * 64 + bg], hv);
            __stcs(&out[(size_t)step * BH + bg * Hh + n], hv);
            __threadfence();   // release: h stores visible before flag
        }
        __syncthreads();

        // ---- publish step, then next step's x-part (no wait needed) ----
        if (t == 0) *(volatile unsigned*)&g_flags[cta * 8] = (unsigned)(step + 1);
        if (step + 1 < STEPS) {
            ZERO_ACC()
            XGEMM(step + 1)
        }
    }
#undef ZERO_ACC
#undef LOADBLK
#undef FMABLK
#undef XGEMM
}

// --------------------------- launch ----------------------------------------
extern "C" void kernel_launch(void* const* d_in, const int* in_sizes, int n_in,
                              void* d_out, int out_size)
{
    const float* x    = (const float*)d_in[0];
    const float* Wx   = (const float*)d_in[1];
    const float* Whs  = (const float*)d_in[2];
    const float* Wht  = (const float*)d_in[3];
    const float* bias = (const float*)d_in[4];
    float*       out  = (float*)d_out;

    cudaFuncSetAttribute(stlstm_kernel,
                         cudaFuncAttributeMaxDynamicSharedMemorySize, SMEM_BYTES);
    stlstm_kernel<<<NCTA, NTHR, SMEM_BYTES>>>(x, Wx, Whs, Wht, bias, out);
}

// round 10
// speedup vs baseline: 1.1622x; 1.1622x over previous
#include <cuda_runtime.h>
#include <cstdint>

// ---------------------------------------------------------------------------
// ST-LSTM persistent kernel, fp32 f32x2. Round 9 = R5 (best, 18.57ms) with ONE
// change: the grid-barrier wait is warp-scoped.
//   - warps 0-7 (consume h[s-1]): each waits on its own 16 producer CTA flags
//   - warps 8-15 (consume h[s-25]): NO wait — ordering guaranteed transitively
//     by the pre-STS __syncthreads (they run next-step h-GEMM during the wait,
//     keeping the fma pipe fed: 2 free warps per SMSP saturate rt=2 FFMA2)
// 128 CTAs x 512 thr. CTA owns 4 h-cols (20 z-cols), full K=1280.
// ---------------------------------------------------------------------------

#define NCTA 128
#define NTHR 512

constexpr int Bb = 64, Ii = 256, Hh = 512;
constexpr int G5H   = 2560;
constexpr int STEPS = 1600;
constexpr int HB    = Hh * Bb;     // 32768
constexpr int XB    = Ii * Bb;     // 16384
constexpr int BH    = Bb * Hh;
constexpr int NPC   = 20;          // z-cols per CTA
constexpr int KSL   = 16;          // k-slices
constexpr int RS    = 1296;        // reduce row stride (floats)

constexpr int W_OFF = 0;                    // 1280*20
constexpr int R_OFF = 25600;                // 16*1296
constexpr int C_OFF = R_OFF + KSL * RS;     // 25*256
constexpr int SM_FLOATS  = C_OFF + 25 * 256;
constexpr int SMEM_BYTES = SM_FLOATS * 4;   // 210,944 B

// --------------------------- device scratch --------------------------------
__device__ float    g_xT[(size_t)STEPS * XB];  // x transposed [tj][i][b]
__device__ float    g_hT[32 * HB];             // h ring [slot][n][b]
__device__ unsigned g_flags[NCTA * 8];         // per-CTA published-step counters
__device__ unsigned g_cnt = 0;                 // init barrier (one-shot, self-reset)
__device__ unsigned g_gen = 0;

// --------------------------- helpers ---------------------------------------
__device__ __forceinline__ void init_barrier() {
    __syncthreads();
    if (threadIdx.x == 0) {
        unsigned gen = *(volatile unsigned*)&g_gen;
        __threadfence();
        unsigned rank = atomicAdd(&g_cnt, 1u);
        if (rank == NCTA - 1) {
            g_cnt = 0;
            __threadfence();
            *(volatile unsigned*)&g_gen = gen + 1u;
        } else {
            while (*(volatile unsigned*)&g_gen == gen) { __nanosleep(64); }
        }
        __threadfence();
    }
    __syncthreads();
}

// warp-scoped wait: lanes 0..15 poll this warp's 16 producer flags until >= k
__device__ __forceinline__ void warp_wait16(int prodbase, int lane, unsigned k) {
    if (lane < 16) {
        const unsigned* p = &g_flags[(prodbase + lane) * 8];
        unsigned v;
        asm volatile("ld.global.cg.u32 %0, [%1];" : "=r"(v) : "l"(p));
        while ((int)(v - k) < 0) {
            __nanosleep(32);
            asm volatile("ld.global.cg.u32 %0, [%1];" : "=r"(v) : "l"(p));
        }
    }
    __syncwarp();
    __threadfence();   // acquire: order flag observation before h loads
}

__device__ __forceinline__ float fexp(float x) {
    float r;
    asm("ex2.approx.f32 %0, %1;" : "=f"(r) : "f"(x * 1.4426950408889634f));
    return r;
}
__device__ __forceinline__ float frcp(float x) {
    float r;
    asm("rcp.approx.f32 %0, %1;" : "=f"(r) : "f"(x));
    return r;
}
__device__ __forceinline__ float fsig(float x)  { return frcp(1.0f + fexp(-x)); }
__device__ __forceinline__ float ftanh(float x) { return 1.0f - 2.0f * frcp(1.0f + fexp(2.0f * x)); }

// --------------------------- kernel ----------------------------------------
__global__ void __launch_bounds__(NTHR, 1)
stlstm_kernel(const float* __restrict__ x,
              const float* __restrict__ Wx,
              const float* __restrict__ Whs,
              const float* __restrict__ Wht,
              const float* __restrict__ bias,
              float* __restrict__ out)
{
    extern __shared__ float sm[];
    float* W_s = sm + W_OFF;
    float* red = sm + R_OFF;
    float* c_s = sm + C_OFF;

    const int t   = threadIdx.x;
    const int cta = blockIdx.x;
    const int nt  = cta;

    // -------- pre-barrier init: flags, x transpose, ring zero, weights ------
    if (t == 0) *(volatile unsigned*)&g_flags[cta * 8] = 0u;
    {
        float* tmp = red;                      // 20736 floats >= 64*257
        for (int tj = cta; tj < STEPS; tj += NCTA) {
            const float* xsrc = x + (size_t)tj * (Bb * Ii);
            for (int idx = t; idx < Bb * Ii; idx += NTHR) {
                int bb = idx >> 8, ii = idx & 255;
                tmp[bb * 257 + ii] = xsrc[idx];
            }
            __syncthreads();
            float* xdst = g_xT + (size_t)tj * XB;
            for (int idx = t; idx < Bb * Ii; idx += NTHR) {
                int ii = idx >> 6, bb = idx & 63;
                xdst[idx] = tmp[bb * 257 + ii];
            }
            __syncthreads();
        }
    }
    {   // zero h-ring slots 7..31 (all early reads land there)
        float* z = g_hT + 7 * HB;
        for (int idx = cta * NTHR + t; idx < 25 * HB; idx += NCTA * NTHR) z[idx] = 0.0f;
    }
    for (int idx = t; idx < 25 * 256; idx += NTHR) c_s[idx] = 0.0f;

    for (int idx = t; idx < 1280 * NPC; idx += NTHR) {
        int k = idx / NPC, c = idx % NPC;
        int g = c >> 2, hc = c & 3;
        int col = g * Hh + nt * 4 + hc;
        float w;
        if (k < Hh)            w = Whs[(size_t)k * G5H + col];
        else if (k < 2 * Hh)   w = Wht[(size_t)(k - Hh) * G5H + col];
        else                   w = Wx [(size_t)(k - 2 * Hh) * G5H + col];
        W_s[idx] = w;
    }

    float ba[5];
    {
        int hc = t & 3;
        #pragma unroll
        for (int g = 0; g < 5; ++g) ba[g] = bias[g * Hh + nt * 4 + hc];
    }

    init_barrier();   // x ready, rings zeroed, flags zeroed everywhere

    // GEMM mapping: thread = (ng, mg, ks); ks warp-uniform.
    const int ng   = t & 1;
    const int mg   = (t >> 1) & 15;
    const int ks   = t >> 5;
    const int lane = t & 31;
    const int b_lo = mg * 4;
    const int ng2  = ng * 2;
    const int khW  = ks * 64;            // W row base, h part
    const int kxW  = 1024 + ks * 16;     // W row base, x part

    const int prodbase = (ks & 7) * 16;  // producer CTA set for warps 0-7

    const int bg  = t >> 2;              // gate phase (t < 256)
    const int hcg = t & 3;

    unsigned long long acc[4][5];
    float4 bufA[4], bufB[4];

#define ZERO_ACC()                                                            \
    {  _Pragma("unroll")                                                      \
       for (int i = 0; i < 4; ++i)                                            \
           _Pragma("unroll")                                                  \
           for (int g = 0; g < 5; ++g) acc[i][g] = 0ull; }

#define LOADBLK(BUF, PA, BLK)                                                 \
    {  _Pragma("unroll")                                                      \
       for (int u = 0; u < 4; ++u)                                            \
           BUF[u] = __ldcg((const float4*)((PA) + ((BLK) * 4 + u) * 64));     \
    }

#define FMABLK(BUF, KWB, BLK)                                                 \
    {  _Pragma("unroll")                                                      \
       for (int u = 0; u < 4; ++u) {                                          \
           const float* wr = W_s + ((KWB) + (BLK) * 4 + u) * NPC + ng2;       \
           unsigned long long w0 = *(const unsigned long long*)(wr);          \
           unsigned long long w1 = *(const unsigned long long*)(wr + 4);      \
           unsigned long long w2 = *(const unsigned long long*)(wr + 8);      \
           unsigned long long w3 = *(const unsigned long long*)(wr + 12);     \
           unsigned long long w4 = *(const unsigned long long*)(wr + 16);     \
           float av[4] = {BUF[u].x, BUF[u].y, BUF[u].z, BUF[u].w};            \
           _Pragma("unroll")                                                  \
           for (int i = 0; i < 4; ++i) {                                      \
               unsigned long long aa;                                         \
               asm("mov.b64 %0, {%1, %1};" : "=l"(aa) : "f"(av[i]));          \
               asm("fma.rn.f32x2 %0, %1, %2, %0;" : "+l"(acc[i][0]) : "l"(aa), "l"(w0)); \
               asm("fma.rn.f32x2 %0, %1, %2, %0;" : "+l"(acc[i][1]) : "l"(aa), "l"(w1)); \
               asm("fma.rn.f32x2 %0, %1, %2, %0;" : "+l"(acc[i][2]) : "l"(aa), "l"(w2)); \
               asm("fma.rn.f32x2 %0, %1, %2, %0;" : "+l"(acc[i][3]) : "l"(aa), "l"(w3)); \
               asm("fma.rn.f32x2 %0, %1, %2, %0;" : "+l"(acc[i][4]) : "l"(aa), "l"(w4)); \
           } } }

#define XGEMM(S)                                                              \
    {  const float* pX = g_xT + (size_t)(S) * XB + (ks * 16) * 64 + b_lo;     \
       LOADBLK(bufA, pX, 0)                                                   \
       LOADBLK(bufB, pX, 1)                                                   \
       FMABLK(bufA, kxW, 0)                                                   \
       LOADBLK(bufA, pX, 2)                                                   \
       FMABLK(bufB, kxW, 1)                                                   \
       LOADBLK(bufB, pX, 3)                                                   \
       FMABLK(bufA, kxW, 2)                                                   \
       FMABLK(bufB, kxW, 3) }

    // prologue: x-part of step 0
    ZERO_ACC()
    XGEMM(0)

    // ---------------- main sequential loop ----------------------------------
    for (int step = 0; step < STEPS; ++step) {

        // ---- h-part GEMM: 16 blocks over this thread's 64 h-rows ----
        // warps 0-7 arrive here having waited (end of prev iter); warps 8-15
        // read h[step-25] (stale, ordering via prior __syncthreads) -> no wait.
        {
            const float* h1  = g_hT + ((step - 1)  & 31) * HB;
            const float* h25 = g_hT + ((step - 25) & 31) * HB;
            const float* pH  = ((ks < 8) ? (h1 + khW * 64)
                                         : (h25 + (khW - 512) * 64)) + b_lo;
            LOADBLK(bufA, pH, 0)
            #pragma unroll 1
            for (int blk = 0; blk < 16; blk += 2) {
                LOADBLK(bufB, pH, blk + 1)
                FMABLK(bufA, khW, blk)
                if (blk + 2 < 16) LOADBLK(bufA, pH, blk + 2)
                FMABLK(bufB, khW, blk + 1)
            }
        }

        __syncthreads();   // red buffer free (previous gate phase done)

        // ---- store partials ----
        {
            float* rrow = red + ks * RS + ng2;
            #pragma unroll
            for (int i = 0; i < 4; ++i) {
                int rb = (b_lo + i) * NPC;
                #pragma unroll
                for (int g = 0; g < 5; ++g)
                    *(float2*)(rrow + rb + g * 4) = *(float2*)&acc[i][g];
            }
        }
        __syncthreads();

        // ---- reduce 16 k-slices + gates (threads 0..255) ----
        if (t < 256) {
            float z[5];
            #pragma unroll
            for (int g = 0; g < 5; ++g) {
                float s = ba[g];
                const float* rp = red + bg * NPC + g * 4 + hcg;
                #pragma unroll
                for (int q = 0; q < KSL; ++q) s += rp[q * RS];
                z[g] = s;
            }
            float cs = c_s[((step + 24) % 25) * 256 + t];
            float ct = c_s[(step % 25) * 256 + t];
            float cc = fsig(z[0]) * ftanh(z[3]) + fsig(z[1]) * cs + fsig(z[2]) * ct;
            float hv = fsig(z[4]) * ftanh(cc);
            c_s[(step % 25) * 256 + t] = cc;

            int n = nt * 4 + hcg;
            out[(size_t)step * BH + bg * Hh + n] = hv;
            g_hT[(step & 31) * HB + n * 64 + bg] = hv;
        }

        // ---- publish (release), then x-part of next step, then scoped wait --
        __syncthreads();
        __threadfence();
        if (t == 0) *(volatile unsigned*)&g_flags[cta * 8] = (unsigned)(step + 1);
        if (step + 1 < STEPS) {
            ZERO_ACC()
            XGEMM(step + 1)
            if (ks < 8) warp_wait16(prodbase, lane, (unsigned)(step + 1));
        }
    }
#undef ZERO_ACC
#undef LOADBLK
#undef FMABLK
#undef XGEMM
}

// --------------------------- launch ----------------------------------------
extern "C" void kernel_launch(void* const* d_in, const int* in_sizes, int n_in,
                              void* d_out, int out_size)
{
    const float* x    = (const float*)d_in[0];
    const float* Wx   = (const float*)d_in[1];
    const float* Whs  = (const float*)d_in[2];
    const float* Wht  = (const float*)d_in[3];
    const float* bias = (const float*)d_in[4];
    float*       out  = (float*)d_out;

    cudaFuncSetAttribute(stlstm_kernel,
                         cudaFuncAttributeMaxDynamicSharedMemorySize, SMEM_BYTES);
    stlstm_kernel<<<NCTA, NTHR, SMEM_BYTES>>>(x, Wx, Whs, Wht, bias, out);
}

// round 11
// speedup vs baseline: 1.1959x; 1.0290x over previous
#include <cuda_runtime.h>
#include <cstdint>

// ---------------------------------------------------------------------------
// ST-LSTM persistent kernel, fp32 f32x2. Round 10: warp-group pipelining.
//  Warps 0-7  (critical): wait flag -> h[s-1] GEMM (64 rows) -> bar1 -> STS
//                         -> bar2 -> reduce+gates -> bar3(256) -> publish
//  Warps 8-15 (slack):    h[s-25] GEMM (64 rows) + ALL x rows (32/warp)
//                         -> bar1 -> STS -> bar2 -> next step immediately
//  Named barriers match by count, so the slack group runs step s+1's GEMM
//  while the critical group is in gates/wait — FMA pipe stays fed through
//  the serial tail and the flag round-trip.
// 128 CTAs x 512 thr. CTA owns 4 h-cols (20 z-cols), full K=1280.
// ---------------------------------------------------------------------------

#define NCTA 128
#define NTHR 512

constexpr int Bb = 64, Ii = 256, Hh = 512;
constexpr int G5H   = 2560;
constexpr int STEPS = 1600;
constexpr int HB    = Hh * Bb;     // 32768
constexpr int XB    = Ii * Bb;     // 16384
constexpr int BH    = Bb * Hh;
constexpr int NPC   = 20;          // z-cols per CTA
constexpr int KSL   = 16;          // k-slices (= warps)
constexpr int RS    = 1296;        // reduce row stride (floats)

constexpr int W_OFF = 0;                    // 1280*20
constexpr int R_OFF = 25600;                // 16*1296
constexpr int C_OFF = R_OFF + KSL * RS;     // 25*256
constexpr int SM_FLOATS  = C_OFF + 25 * 256;
constexpr int SMEM_BYTES = SM_FLOATS * 4;   // 210,944 B

// --------------------------- device scratch --------------------------------
__device__ float    g_xT[(size_t)STEPS * XB];  // x transposed [tj][i][b]
__device__ float    g_hT[32 * HB];             // h ring [slot][n][b]
__device__ unsigned g_flags[NCTA * 8];         // per-CTA published-step counters
__device__ unsigned g_cnt = 0;                 // init barrier (one-shot, self-reset)
__device__ unsigned g_gen = 0;

// --------------------------- helpers ---------------------------------------
__device__ __forceinline__ void init_barrier() {
    __syncthreads();
    if (threadIdx.x == 0) {
        unsigned gen = *(volatile unsigned*)&g_gen;
        __threadfence();
        unsigned rank = atomicAdd(&g_cnt, 1u);
        if (rank == NCTA - 1) {
            g_cnt = 0;
            __threadfence();
            *(volatile unsigned*)&g_gen = gen + 1u;
        } else {
            while (*(volatile unsigned*)&g_gen == gen) { __nanosleep(64); }
        }
        __threadfence();
    }
    __syncthreads();
}

// warp-scoped wait: lanes 0..15 poll this warp's 16 producer flags until >= k
__device__ __forceinline__ void warp_wait16(int prodbase, int lane, unsigned k) {
    if (lane < 16) {
        const unsigned* p = &g_flags[(prodbase + lane) * 8];
        unsigned v;
        asm volatile("ld.global.cg.u32 %0, [%1];" : "=r"(v) : "l"(p));
        while ((int)(v - k) < 0) {
            __nanosleep(32);
            asm volatile("ld.global.cg.u32 %0, [%1];" : "=r"(v) : "l"(p));
        }
    }
    __syncwarp();
    __threadfence();   // acquire: order flag observation before h loads
}

#define BAR1() asm volatile("bar.sync 1, 512;" ::: "memory")
#define BAR2() asm volatile("bar.sync 2, 512;" ::: "memory")
#define BAR3() asm volatile("bar.sync 3, 256;" ::: "memory")

__device__ __forceinline__ float fexp(float x) {
    float r;
    asm("ex2.approx.f32 %0, %1;" : "=f"(r) : "f"(x * 1.4426950408889634f));
    return r;
}
__device__ __forceinline__ float frcp(float x) {
    float r;
    asm("rcp.approx.f32 %0, %1;" : "=f"(r) : "f"(x));
    return r;
}
__device__ __forceinline__ float fsig(float x)  { return frcp(1.0f + fexp(-x)); }
__device__ __forceinline__ float ftanh(float x) { return 1.0f - 2.0f * frcp(1.0f + fexp(2.0f * x)); }

// --------------------------- kernel ----------------------------------------
__global__ void __launch_bounds__(NTHR, 1)
stlstm_kernel(const float* __restrict__ x,
              const float* __restrict__ Wx,
              const float* __restrict__ Whs,
              const float* __restrict__ Wht,
              const float* __restrict__ bias,
              float* __restrict__ out)
{
    extern __shared__ float sm[];
    float* W_s = sm + W_OFF;
    float* red = sm + R_OFF;
    float* c_s = sm + C_OFF;

    const int t   = threadIdx.x;
    const int cta = blockIdx.x;
    const int nt  = cta;

    // -------- pre-barrier init: flags, x transpose, ring zero, weights ------
    if (t == 0) *(volatile unsigned*)&g_flags[cta * 8] = 0u;
    {
        float* tmp = red;                      // 20736 floats >= 64*257
        for (int tj = cta; tj < STEPS; tj += NCTA) {
            const float* xsrc = x + (size_t)tj * (Bb * Ii);
            for (int idx = t; idx < Bb * Ii; idx += NTHR) {
                int bb = idx >> 8, ii = idx & 255;
                tmp[bb * 257 + ii] = xsrc[idx];
            }
            __syncthreads();
            float* xdst = g_xT + (size_t)tj * XB;
            for (int idx = t; idx < Bb * Ii; idx += NTHR) {
                int ii = idx >> 6, bb = idx & 63;
                xdst[idx] = tmp[bb * 257 + ii];
            }
            __syncthreads();
        }
    }
    {   // zero h-ring slots 7..31 (all early reads land there)
        float* z = g_hT + 7 * HB;
        for (int idx = cta * NTHR + t; idx < 25 * HB; idx += NCTA * NTHR) z[idx] = 0.0f;
    }
    for (int idx = t; idx < 25 * 256; idx += NTHR) c_s[idx] = 0.0f;

    for (int idx = t; idx < 1280 * NPC; idx += NTHR) {
        int k = idx / NPC, c = idx % NPC;
        int g = c >> 2, hc = c & 3;
        int col = g * Hh + nt * 4 + hc;
        float w;
        if (k < Hh)            w = Whs[(size_t)k * G5H + col];
        else if (k < 2 * Hh)   w = Wht[(size_t)(k - Hh) * G5H + col];
        else                   w = Wx [(size_t)(k - 2 * Hh) * G5H + col];
        W_s[idx] = w;
    }

    float ba[5];
    {
        int hc = t & 3;
        #pragma unroll
        for (int g = 0; g < 5; ++g) ba[g] = bias[g * Hh + nt * 4 + hc];
    }

    init_barrier();   // x ready, rings zeroed, flags zeroed everywhere

    // GEMM mapping: thread = (ng, mg, ks); ks warp-uniform.
    const int ng   = t & 1;
    const int mg   = (t >> 1) & 15;
    const int ks   = t >> 5;
    const int lane = t & 31;
    const int b_lo = mg * 4;
    const int ng2  = ng * 2;
    const int khW  = ks * 64;                  // W row base, h part
    const int kxW  = 1024 + (ks - 8) * 32;     // W row base, x part (warps 8-15)

    const int prodbase = (ks & 7) * 16;        // producer CTA set (warps 0-7)

    const int bg  = t >> 2;                    // gate phase (t < 256)
    const int hcg = t & 3;

    unsigned long long acc[4][5];
    float4 bufA[4], bufB[4];

#define ZERO_ACC()                                                            \
    {  _Pragma("unroll")                                                      \
       for (int i = 0; i < 4; ++i)                                            \
           _Pragma("unroll")                                                  \
           for (int g = 0; g < 5; ++g) acc[i][g] = 0ull; }

#define LOADBLK(BUF, PA, BLK)                                                 \
    {  _Pragma("unroll")                                                      \
       for (int u = 0; u < 4; ++u)                                            \
           BUF[u] = __ldcg((const float4*)((PA) + ((BLK) * 4 + u) * 64));     \
    }

#define FMABLK(BUF, KWB, BLK)                                                 \
    {  _Pragma("unroll")                                                      \
       for (int u = 0; u < 4; ++u) {                                          \
           const float* wr = W_s + ((KWB) + (BLK) * 4 + u) * NPC + ng2;       \
           unsigned long long w0 = *(const unsigned long long*)(wr);          \
           unsigned long long w1 = *(const unsigned long long*)(wr + 4);      \
           unsigned long long w2 = *(const unsigned long long*)(wr + 8);      \
           unsigned long long w3 = *(const unsigned long long*)(wr + 12);     \
           unsigned long long w4 = *(const unsigned long long*)(wr + 16);     \
           float av[4] = {BUF[u].x, BUF[u].y, BUF[u].z, BUF[u].w};            \
           _Pragma("unroll")                                                  \
           for (int i = 0; i < 4; ++i) {                                      \
               unsigned long long aa;                                         \
               asm("mov.b64 %0, {%1, %1};" : "=l"(aa) : "f"(av[i]));          \
               asm("fma.rn.f32x2 %0, %1, %2, %0;" : "+l"(acc[i][0]) : "l"(aa), "l"(w0)); \
               asm("fma.rn.f32x2 %0, %1, %2, %0;" : "+l"(acc[i][1]) : "l"(aa), "l"(w1)); \
               asm("fma.rn.f32x2 %0, %1, %2, %0;" : "+l"(acc[i][2]) : "l"(aa), "l"(w2)); \
               asm("fma.rn.f32x2 %0, %1, %2, %0;" : "+l"(acc[i][3]) : "l"(aa), "l"(w3)); \
               asm("fma.rn.f32x2 %0, %1, %2, %0;" : "+l"(acc[i][4]) : "l"(aa), "l"(w4)); \
           } } }

    // ---------------- main sequential loop ----------------------------------
    for (int step = 0; step < STEPS; ++step) {

        ZERO_ACC()

        if (ks < 8) {
            // ===== critical group: wait, then h[s-1] GEMM (16 blocks) =====
            if (step > 0) warp_wait16(prodbase, lane, (unsigned)step);
            {
                const float* pH = g_hT + ((step - 1) & 31) * HB + khW * 64 + b_lo;
                LOADBLK(bufA, pH, 0)
                #pragma unroll 1
                for (int blk = 0; blk < 16; blk += 2) {
                    LOADBLK(bufB, pH, blk + 1)
                    FMABLK(bufA, khW, blk)
                    if (blk + 2 < 16) LOADBLK(bufA, pH, blk + 2)
                    FMABLK(bufB, khW, blk + 1)
                }
            }
        } else {
            // ===== slack group: h[s-25] GEMM (16 blocks) + x (8 blocks) =====
            {
                const float* pH = g_hT + ((step - 25) & 31) * HB
                                  + (khW - 512) * 64 + b_lo;
                LOADBLK(bufA, pH, 0)
                #pragma unroll 1
                for (int blk = 0; blk < 16; blk += 2) {
                    LOADBLK(bufB, pH, blk + 1)
                    FMABLK(bufA, khW, blk)
                    if (blk + 2 < 16) LOADBLK(bufA, pH, blk + 2)
                    FMABLK(bufB, khW, blk + 1)
                }
            }
            {
                const float* pX = g_xT + (size_t)step * XB
                                  + (kxW - 1024) * 64 + b_lo;
                LOADBLK(bufA, pX, 0)
                #pragma unroll 1
                for (int blk = 0; blk < 8; blk += 2) {
                    LOADBLK(bufB, pX, blk + 1)
                    FMABLK(bufA, kxW, blk)
                    if (blk + 2 < 8) LOADBLK(bufA, pX, blk + 2)
                    FMABLK(bufB, kxW, blk + 1)
                }
            }
        }

        BAR1();   // gates(step-1) done reading red (warps 0-7 arrive post-gates)

        // ---- store partials ----
        {
            float* rrow = red + ks * RS + ng2;
            #pragma unroll
            for (int i = 0; i < 4; ++i) {
                int rb = (b_lo + i) * NPC;
                #pragma unroll
                for (int g = 0; g < 5; ++g)
                    *(float2*)(rrow + rb + g * 4) = *(float2*)&acc[i][g];
            }
        }

        BAR2();   // all partials visible

        if (ks < 8) {
            // ---- reduce 16 k-slices + gates (threads 0..255) ----
            float z[5];
            #pragma unroll
            for (int g = 0; g < 5; ++g) {
                float s = ba[g];
                const float* rp = red + bg * NPC + g * 4 + hcg;
                #pragma unroll
                for (int q = 0; q < KSL; ++q) s += rp[q * RS];
                z[g] = s;
            }
            float cs = c_s[((step + 24) % 25) * 256 + t];
            float ct = c_s[(step % 25) * 256 + t];
            float cc = fsig(z[0]) * ftanh(z[3]) + fsig(z[1]) * cs + fsig(z[2]) * ct;
            float hv = fsig(z[4]) * ftanh(cc);
            c_s[(step % 25) * 256 + t] = cc;

            int n = nt * 4 + hcg;
            out[(size_t)step * BH + bg * Hh + n] = hv;
            g_hT[(step & 31) * HB + n * 64 + bg] = hv;

            BAR3();   // group-private: all 256 gate stores done
            if (t == 0) {
                __threadfence();   // release
                *(volatile unsigned*)&g_flags[cta * 8] = (unsigned)(step + 1);
            }
        }
        // slack group: no tail — straight into step+1's GEMM
    }
#undef ZERO_ACC
#undef LOADBLK
#undef FMABLK
}

// --------------------------- launch ----------------------------------------
extern "C" void kernel_launch(void* const* d_in, const int* in_sizes, int n_in,
                              void* d_out, int out_size)
{
    const float* x    = (const float*)d_in[0];
    const float* Wx   = (const float*)d_in[1];
    const float* Whs  = (const float*)d_in[2];
    const float* Wht  = (const float*)d_in[3];
    const float* bias = (const float*)d_in[4];
    float*       out  = (float*)d_out;

    cudaFuncSetAttribute(stlstm_kernel,
                         cudaFuncAttributeMaxDynamicSharedMemorySize, SMEM_BYTES);
    stlstm_kernel<<<NCTA, NTHR, SMEM_BYTES>>>(x, Wx, Whs, Wht, bias, out);
}

// round 12
// speedup vs baseline: 1.2154x; 1.0163x over previous
#include <cuda_runtime.h>
#include <cstdint>

// ---------------------------------------------------------------------------
// ST-LSTM persistent kernel, fp32 f32x2. Round 11 = R10 (warp-group pipeline)
// + critical-chain trims:
//  - st.release.gpu publish / ld.acquire.gpu polls (no membar on hot path)
//  - tail reorder: h-store -> BAR3 -> publish, THEN out[] + c_s stores
//  - adaptive poll (tight spin 16 iters, then nanosleep)
// Warps 0-7 critical (h[s-1] + gates), warps 8-15 slack (h[s-25] + all x).
// 128 CTAs x 512 thr. CTA owns 4 h-cols (20 z-cols), full K=1280.
// ---------------------------------------------------------------------------

#define NCTA 128
#define NTHR 512

constexpr int Bb = 64, Ii = 256, Hh = 512;
constexpr int G5H   = 2560;
constexpr int STEPS = 1600;
constexpr int HB    = Hh * Bb;     // 32768
constexpr int XB    = Ii * Bb;     // 16384
constexpr int BH    = Bb * Hh;
constexpr int NPC   = 20;          // z-cols per CTA
constexpr int KSL   = 16;          // k-slices (= warps)
constexpr int RS    = 1296;        // reduce row stride (floats)

constexpr int W_OFF = 0;                    // 1280*20
constexpr int R_OFF = 25600;                // 16*1296
constexpr int C_OFF = R_OFF + KSL * RS;     // 25*256
constexpr int SM_FLOATS  = C_OFF + 25 * 256;
constexpr int SMEM_BYTES = SM_FLOATS * 4;   // 210,944 B

// --------------------------- device scratch --------------------------------
__device__ float    g_xT[(size_t)STEPS * XB];  // x transposed [tj][i][b]
__device__ float    g_hT[32 * HB];             // h ring [slot][n][b]
__device__ unsigned g_flags[NCTA * 8];         // per-CTA published-step counters
__device__ unsigned g_cnt = 0;                 // init barrier (one-shot, self-reset)
__device__ unsigned g_gen = 0;

// --------------------------- helpers ---------------------------------------
__device__ __forceinline__ void init_barrier() {
    __syncthreads();
    if (threadIdx.x == 0) {
        unsigned gen = *(volatile unsigned*)&g_gen;
        __threadfence();
        unsigned rank = atomicAdd(&g_cnt, 1u);
        if (rank == NCTA - 1) {
            g_cnt = 0;
            __threadfence();
            *(volatile unsigned*)&g_gen = gen + 1u;
        } else {
            while (*(volatile unsigned*)&g_gen == gen) { __nanosleep(64); }
        }
        __threadfence();
    }
    __syncthreads();
}

// warp-scoped wait: lanes 0..15 poll producer flags with acquire loads.
// Tight spin first 16 rounds (common near-ready case), then nanosleep backoff.
__device__ __forceinline__ void warp_wait16(int prodbase, int lane, unsigned k) {
    if (lane < 16) {
        const unsigned* p = &g_flags[(prodbase + lane) * 8];
        unsigned v;
        int spins = 0;
        for (;;) {
            asm volatile("ld.acquire.gpu.global.u32 %0, [%1];" : "=r"(v) : "l"(p));
            if ((int)(v - k) >= 0) break;
            if (++spins > 16) __nanosleep(32);
        }
    }
    __syncwarp();
}

#define BAR1() asm volatile("bar.sync 1, 512;" ::: "memory")
#define BAR2() asm volatile("bar.sync 2, 512;" ::: "memory")
#define BAR3() asm volatile("bar.sync 3, 256;" ::: "memory")

__device__ __forceinline__ float fexp(float x) {
    float r;
    asm("ex2.approx.f32 %0, %1;" : "=f"(r) : "f"(x * 1.4426950408889634f));
    return r;
}
__device__ __forceinline__ float frcp(float x) {
    float r;
    asm("rcp.approx.f32 %0, %1;" : "=f"(r) : "f"(x));
    return r;
}
__device__ __forceinline__ float fsig(float x)  { return frcp(1.0f + fexp(-x)); }
__device__ __forceinline__ float ftanh(float x) { return 1.0f - 2.0f * frcp(1.0f + fexp(2.0f * x)); }

// --------------------------- kernel ----------------------------------------
__global__ void __launch_bounds__(NTHR, 1)
stlstm_kernel(const float* __restrict__ x,
              const float* __restrict__ Wx,
              const float* __restrict__ Whs,
              const float* __restrict__ Wht,
              const float* __restrict__ bias,
              float* __restrict__ out)
{
    extern __shared__ float sm[];
    float* W_s = sm + W_OFF;
    float* red = sm + R_OFF;
    float* c_s = sm + C_OFF;

    const int t   = threadIdx.x;
    const int cta = blockIdx.x;
    const int nt  = cta;

    // -------- pre-barrier init: flags, x transpose, ring zero, weights ------
    if (t == 0) *(volatile unsigned*)&g_flags[cta * 8] = 0u;
    {
        float* tmp = red;                      // 20736 floats >= 64*257
        for (int tj = cta; tj < STEPS; tj += NCTA) {
            const float* xsrc = x + (size_t)tj * (Bb * Ii);
            for (int idx = t; idx < Bb * Ii; idx += NTHR) {
                int bb = idx >> 8, ii = idx & 255;
                tmp[bb * 257 + ii] = xsrc[idx];
            }
            __syncthreads();
            float* xdst = g_xT + (size_t)tj * XB;
            for (int idx = t; idx < Bb * Ii; idx += NTHR) {
                int ii = idx >> 6, bb = idx & 63;
                xdst[idx] = tmp[bb * 257 + ii];
            }
            __syncthreads();
        }
    }
    {   // zero h-ring slots 7..31 (all early reads land there)
        float* z = g_hT + 7 * HB;
        for (int idx = cta * NTHR + t; idx < 25 * HB; idx += NCTA * NTHR) z[idx] = 0.0f;
    }
    for (int idx = t; idx < 25 * 256; idx += NTHR) c_s[idx] = 0.0f;

    for (int idx = t; idx < 1280 * NPC; idx += NTHR) {
        int k = idx / NPC, c = idx % NPC;
        int g = c >> 2, hc = c & 3;
        int col = g * Hh + nt * 4 + hc;
        float w;
        if (k < Hh)            w = Whs[(size_t)k * G5H + col];
        else if (k < 2 * Hh)   w = Wht[(size_t)(k - Hh) * G5H + col];
        else                   w = Wx [(size_t)(k - 2 * Hh) * G5H + col];
        W_s[idx] = w;
    }

    float ba[5];
    {
        int hc = t & 3;
        #pragma unroll
        for (int g = 0; g < 5; ++g) ba[g] = bias[g * Hh + nt * 4 + hc];
    }

    init_barrier();   // x ready, rings zeroed, flags zeroed everywhere

    // GEMM mapping: thread = (ng, mg, ks); ks warp-uniform.
    const int ng   = t & 1;
    const int mg   = (t >> 1) & 15;
    const int ks   = t >> 5;
    const int lane = t & 31;
    const int b_lo = mg * 4;
    const int ng2  = ng * 2;
    const int khW  = ks * 64;                  // W row base, h part
    const int kxW  = 1024 + (ks - 8) * 32;     // W row base, x part (warps 8-15)

    const int prodbase = (ks & 7) * 16;        // producer CTA set (warps 0-7)

    const int bg  = t >> 2;                    // gate phase (t < 256)
    const int hcg = t & 3;

    unsigned long long acc[4][5];
    float4 bufA[4], bufB[4];

#define ZERO_ACC()                                                            \
    {  _Pragma("unroll")                                                      \
       for (int i = 0; i < 4; ++i)                                            \
           _Pragma("unroll")                                                  \
           for (int g = 0; g < 5; ++g) acc[i][g] = 0ull; }

#define LOADBLK(BUF, PA, BLK)                                                 \
    {  _Pragma("unroll")                                                      \
       for (int u = 0; u < 4; ++u)                                            \
           BUF[u] = __ldcg((const float4*)((PA) + ((BLK) * 4 + u) * 64));     \
    }

#define FMABLK(BUF, KWB, BLK)                                                 \
    {  _Pragma("unroll")                                                      \
       for (int u = 0; u < 4; ++u) {                                          \
           const float* wr = W_s + ((KWB) + (BLK) * 4 + u) * NPC + ng2;       \
           unsigned long long w0 = *(const unsigned long long*)(wr);          \
           unsigned long long w1 = *(const unsigned long long*)(wr + 4);      \
           unsigned long long w2 = *(const unsigned long long*)(wr + 8);      \
           unsigned long long w3 = *(const unsigned long long*)(wr + 12);     \
           unsigned long long w4 = *(const unsigned long long*)(wr + 16);     \
           float av[4] = {BUF[u].x, BUF[u].y, BUF[u].z, BUF[u].w};            \
           _Pragma("unroll")                                                  \
           for (int i = 0; i < 4; ++i) {                                      \
               unsigned long long aa;                                         \
               asm("mov.b64 %0, {%1, %1};" : "=l"(aa) : "f"(av[i]));          \
               asm("fma.rn.f32x2 %0, %1, %2, %0;" : "+l"(acc[i][0]) : "l"(aa), "l"(w0)); \
               asm("fma.rn.f32x2 %0, %1, %2, %0;" : "+l"(acc[i][1]) : "l"(aa), "l"(w1)); \
               asm("fma.rn.f32x2 %0, %1, %2, %0;" : "+l"(acc[i][2]) : "l"(aa), "l"(w2)); \
               asm("fma.rn.f32x2 %0, %1, %2, %0;" : "+l"(acc[i][3]) : "l"(aa), "l"(w3)); \
               asm("fma.rn.f32x2 %0, %1, %2, %0;" : "+l"(acc[i][4]) : "l"(aa), "l"(w4)); \
           } } }

    // ---------------- main sequential loop ----------------------------------
    for (int step = 0; step < STEPS; ++step) {

        ZERO_ACC()

        if (ks < 8) {
            // ===== critical group: wait, then h[s-1] GEMM (16 blocks) =====
            if (step > 0) warp_wait16(prodbase, lane, (unsigned)step);
            {
                const float* pH = g_hT + ((step - 1) & 31) * HB + khW * 64 + b_lo;
                LOADBLK(bufA, pH, 0)
                #pragma unroll 1
                for (int blk = 0; blk < 16; blk += 2) {
                    LOADBLK(bufB, pH, blk + 1)
                    FMABLK(bufA, khW, blk)
                    if (blk + 2 < 16) LOADBLK(bufA, pH, blk + 2)
                    FMABLK(bufB, khW, blk + 1)
                }
            }
        } else {
            // ===== slack group: h[s-25] GEMM (16 blocks) + x (8 blocks) =====
            {
                const float* pH = g_hT + ((step - 25) & 31) * HB
                                  + (khW - 512) * 64 + b_lo;
                LOADBLK(bufA, pH, 0)
                #pragma unroll 1
                for (int blk = 0; blk < 16; blk += 2) {
                    LOADBLK(bufB, pH, blk + 1)
                    FMABLK(bufA, khW, blk)
                    if (blk + 2 < 16) LOADBLK(bufA, pH, blk + 2)
                    FMABLK(bufB, khW, blk + 1)
                }
            }
            {
                const float* pX = g_xT + (size_t)step * XB
                                  + (kxW - 1024) * 64 + b_lo;
                LOADBLK(bufA, pX, 0)
                #pragma unroll 1
                for (int blk = 0; blk < 8; blk += 2) {
                    LOADBLK(bufB, pX, blk + 1)
                    FMABLK(bufA, kxW, blk)
                    if (blk + 2 < 8) LOADBLK(bufA, pX, blk + 2)
                    FMABLK(bufB, kxW, blk + 1)
                }
            }
        }

        BAR1();   // gates(step-1) done reading red (warps 0-7 arrive post-gates)

        // ---- store partials ----
        {
            float* rrow = red + ks * RS + ng2;
            #pragma unroll
            for (int i = 0; i < 4; ++i) {
                int rb = (b_lo + i) * NPC;
                #pragma unroll
                for (int g = 0; g < 5; ++g)
                    *(float2*)(rrow + rb + g * 4) = *(float2*)&acc[i][g];
            }
        }

        BAR2();   // all partials visible

        if (ks < 8) {
            // ---- reduce 16 k-slices + gates (threads 0..255) ----
            float z[5];
            #pragma unroll
            for (int g = 0; g < 5; ++g) {
                float s = ba[g];
                const float* rp = red + bg * NPC + g * 4 + hcg;
                #pragma unroll
                for (int q = 0; q < KSL; ++q) s += rp[q * RS];
                z[g] = s;
            }
            float cs = c_s[((step + 24) % 25) * 256 + t];
            float ct = c_s[(step % 25) * 256 + t];
            float cc = fsig(z[0]) * ftanh(z[3]) + fsig(z[1]) * cs + fsig(z[2]) * ct;
            float hv = fsig(z[4]) * ftanh(cc);

            // publish-critical store FIRST
            int n = nt * 4 + hcg;
            g_hT[(step & 31) * HB + n * 64 + bg] = hv;

            BAR3();   // all 256 h stores done
            if (t == 0) {
                unsigned k1 = (unsigned)(step + 1);
                asm volatile("st.release.gpu.global.u32 [%0], %1;"
                             :: "l"(&g_flags[cta * 8]), "r"(k1) : "memory");
            }

            // off-critical-path stores AFTER publish
            c_s[(step % 25) * 256 + t] = cc;
            out[(size_t)step * BH + bg * Hh + n] = hv;
        }
        // slack group: no tail — straight into step+1's GEMM
    }
#undef ZERO_ACC
#undef LOADBLK
#undef FMABLK
}

// --------------------------- launch ----------------------------------------
extern "C" void kernel_launch(void* const* d_in, const int* in_sizes, int n_in,
                              void* d_out, int out_size)
{
    const float* x    = (const float*)d_in[0];
    const float* Wx   = (const float*)d_in[1];
    const float* Whs  = (const float*)d_in[2];
    const float* Wht  = (const float*)d_in[3];
    const float* bias = (const float*)d_in[4];
    float*       out  = (float*)d_out;

    cudaFuncSetAttribute(stlstm_kernel,
                         cudaFuncAttributeMaxDynamicSharedMemorySize, SMEM_BYTES);
    stlstm_kernel<<<NCTA, NTHR, SMEM_BYTES>>>(x, Wx, Whs, Wht, bias, out);
}

// round 13
// speedup vs baseline: 1.2266x; 1.0092x over previous
#include <cuda_runtime.h>
#include <cstdint>

// ---------------------------------------------------------------------------
// ST-LSTM persistent kernel, fp32 f32x2. Round 12: symmetric warps with
// dependency-ordered phases.
//  Every warp: [32 h(s-25)-rows + 16 x-rows]  (independent -> runs right after
//              BAR2, covering gates/publish/RT)
//              -> wait on 8 producer flags (steady state: already set)
//              -> [32 h(s-1)-rows]  at FULL 4-warps/SMSP rate
//  -> BAR1 -> STS -> BAR2 -> gates (warps 0-7) -> BAR3 -> release-publish.
// 128 CTAs x 512 thr. CTA owns 4 h-cols (20 z-cols), full K=1280.
// ---------------------------------------------------------------------------

#define NCTA 128
#define NTHR 512

constexpr int Bb = 64, Ii = 256, Hh = 512;
constexpr int G5H   = 2560;
constexpr int STEPS = 1600;
constexpr int HB    = Hh * Bb;     // 32768
constexpr int XB    = Ii * Bb;     // 16384
constexpr int BH    = Bb * Hh;
constexpr int NPC   = 20;          // z-cols per CTA
constexpr int KSL   = 16;          // k-slices (= warps)
constexpr int RS    = 1296;        // reduce row stride (floats)

constexpr int W_OFF = 0;                    // 1280*20
constexpr int R_OFF = 25600;                // 16*1296
constexpr int C_OFF = R_OFF + KSL * RS;     // 25*256
constexpr int SM_FLOATS  = C_OFF + 25 * 256;
constexpr int SMEM_BYTES = SM_FLOATS * 4;   // 210,944 B

// --------------------------- device scratch --------------------------------
__device__ float    g_xT[(size_t)STEPS * XB];  // x transposed [tj][i][b]
__device__ float    g_hT[32 * HB];             // h ring [slot][n][b]
__device__ unsigned g_flags[NCTA * 8];         // per-CTA published-step counters
__device__ unsigned g_cnt = 0;                 // init barrier (one-shot, self-reset)
__device__ unsigned g_gen = 0;

// --------------------------- helpers ---------------------------------------
__device__ __forceinline__ void init_barrier() {
    __syncthreads();
    if (threadIdx.x == 0) {
        unsigned gen = *(volatile unsigned*)&g_gen;
        __threadfence();
        unsigned rank = atomicAdd(&g_cnt, 1u);
        if (rank == NCTA - 1) {
            g_cnt = 0;
            __threadfence();
            *(volatile unsigned*)&g_gen = gen + 1u;
        } else {
            while (*(volatile unsigned*)&g_gen == gen) { __nanosleep(64); }
        }
        __threadfence();
    }
    __syncthreads();
}

// warp-scoped wait: lanes 0..7 poll this warp's 8 producer flags (acquire).
__device__ __forceinline__ void warp_wait8(int prodbase, int lane, unsigned k) {
    if (lane < 8) {
        const unsigned* p = &g_flags[(prodbase + lane) * 8];
        unsigned v;
        int spins = 0;
        for (;;) {
            asm volatile("ld.acquire.gpu.global.u32 %0, [%1];" : "=r"(v) : "l"(p));
            if ((int)(v - k) >= 0) break;
            if (++spins > 16) __nanosleep(32);
        }
    }
    __syncwarp();
}

#define BAR1() asm volatile("bar.sync 1, 512;" ::: "memory")
#define BAR2() asm volatile("bar.sync 2, 512;" ::: "memory")
#define BAR3() asm volatile("bar.sync 3, 256;" ::: "memory")

__device__ __forceinline__ float fexp(float x) {
    float r;
    asm("ex2.approx.f32 %0, %1;" : "=f"(r) : "f"(x * 1.4426950408889634f));
    return r;
}
__device__ __forceinline__ float frcp(float x) {
    float r;
    asm("rcp.approx.f32 %0, %1;" : "=f"(r) : "f"(x));
    return r;
}
__device__ __forceinline__ float fsig(float x)  { return frcp(1.0f + fexp(-x)); }
__device__ __forceinline__ float ftanh(float x) { return 1.0f - 2.0f * frcp(1.0f + fexp(2.0f * x)); }

// --------------------------- kernel ----------------------------------------
__global__ void __launch_bounds__(NTHR, 1)
stlstm_kernel(const float* __restrict__ x,
              const float* __restrict__ Wx,
              const float* __restrict__ Whs,
              const float* __restrict__ Wht,
              const float* __restrict__ bias,
              float* __restrict__ out)
{
    extern __shared__ float sm[];
    float* W_s = sm + W_OFF;
    float* red = sm + R_OFF;
    float* c_s = sm + C_OFF;

    const int t   = threadIdx.x;
    const int cta = blockIdx.x;
    const int nt  = cta;

    // -------- pre-barrier init: flags, x transpose, ring zero, weights ------
    if (t == 0) *(volatile unsigned*)&g_flags[cta * 8] = 0u;
    {
        float* tmp = red;                      // 20736 floats >= 64*257
        for (int tj = cta; tj < STEPS; tj += NCTA) {
            const float* xsrc = x + (size_t)tj * (Bb * Ii);
            for (int idx = t; idx < Bb * Ii; idx += NTHR) {
                int bb = idx >> 8, ii = idx & 255;
                tmp[bb * 257 + ii] = xsrc[idx];
            }
            __syncthreads();
            float* xdst = g_xT + (size_t)tj * XB;
            for (int idx = t; idx < Bb * Ii; idx += NTHR) {
                int ii = idx >> 6, bb = idx & 63;
                xdst[idx] = tmp[bb * 257 + ii];
            }
            __syncthreads();
        }
    }
    {   // zero h-ring slots 7..31 (all early reads land there)
        float* z = g_hT + 7 * HB;
        for (int idx = cta * NTHR + t; idx < 25 * HB; idx += NCTA * NTHR) z[idx] = 0.0f;
    }
    for (int idx = t; idx < 25 * 256; idx += NTHR) c_s[idx] = 0.0f;

    for (int idx = t; idx < 1280 * NPC; idx += NTHR) {
        int k = idx / NPC, c = idx % NPC;
        int g = c >> 2, hc = c & 3;
        int col = g * Hh + nt * 4 + hc;
        float w;
        if (k < Hh)            w = Whs[(size_t)k * G5H + col];
        else if (k < 2 * Hh)   w = Wht[(size_t)(k - Hh) * G5H + col];
        else                   w = Wx [(size_t)(k - 2 * Hh) * G5H + col];
        W_s[idx] = w;
    }

    float ba[5];
    {
        int hc = t & 3;
        #pragma unroll
        for (int g = 0; g < 5; ++g) ba[g] = bias[g * Hh + nt * 4 + hc];
    }

    init_barrier();   // x ready, rings zeroed, flags zeroed everywhere

    // GEMM mapping: thread = (ng, mg, ks); ks warp-uniform.
    // Warp ks owns: h1 rows [ks*32,+32), h25 rows [512+ks*32,+32),
    //               x rows [1024+ks*16,+16).  (80 rows = 20 blocks)
    const int ng    = t & 1;
    const int mg    = (t >> 1) & 15;
    const int ks    = t >> 5;
    const int lane  = t & 31;
    const int b_lo  = mg * 4;
    const int ng2   = ng * 2;
    const int kh1W  = ks * 32;           // W row base, h1 part
    const int kh25W = 512 + ks * 32;     // W row base, h25 part
    const int kxW   = 1024 + ks * 16;    // W row base, x part

    const int prodbase = ks * 8;         // 8 producer CTAs (h-cols ks*32..+31)

    const int bg  = t >> 2;              // gate phase (t < 256)
    const int hcg = t & 3;

    unsigned long long acc[4][5];
    float4 bufA[4], bufB[4];

#define ZERO_ACC()                                                            \
    {  _Pragma("unroll")                                                      \
       for (int i = 0; i < 4; ++i)                                            \
           _Pragma("unroll")                                                  \
           for (int g = 0; g < 5; ++g) acc[i][g] = 0ull; }

#define LOADBLK(BUF, PA, BLK)                                                 \
    {  _Pragma("unroll")                                                      \
       for (int u = 0; u < 4; ++u)                                            \
           BUF[u] = __ldcg((const float4*)((PA) + ((BLK) * 4 + u) * 64));     \
    }

#define FMABLK(BUF, KWB, BLK)                                                 \
    {  _Pragma("unroll")                                                      \
       for (int u = 0; u < 4; ++u) {                                          \
           const float* wr = W_s + ((KWB) + (BLK) * 4 + u) * NPC + ng2;       \
           unsigned long long w0 = *(const unsigned long long*)(wr);          \
           unsigned long long w1 = *(const unsigned long long*)(wr + 4);      \
           unsigned long long w2 = *(const unsigned long long*)(wr + 8);      \
           unsigned long long w3 = *(const unsigned long long*)(wr + 12);     \
           unsigned long long w4 = *(const unsigned long long*)(wr + 16);     \
           float av[4] = {BUF[u].x, BUF[u].y, BUF[u].z, BUF[u].w};            \
           _Pragma("unroll")                                                  \
           for (int i = 0; i < 4; ++i) {                                      \
               unsigned long long aa;                                         \
               asm("mov.b64 %0, {%1, %1};" : "=l"(aa) : "f"(av[i]));          \
               asm("fma.rn.f32x2 %0, %1, %2, %0;" : "+l"(acc[i][0]) : "l"(aa), "l"(w0)); \
               asm("fma.rn.f32x2 %0, %1, %2, %0;" : "+l"(acc[i][1]) : "l"(aa), "l"(w1)); \
               asm("fma.rn.f32x2 %0, %1, %2, %0;" : "+l"(acc[i][2]) : "l"(aa), "l"(w2)); \
               asm("fma.rn.f32x2 %0, %1, %2, %0;" : "+l"(acc[i][3]) : "l"(aa), "l"(w3)); \
               asm("fma.rn.f32x2 %0, %1, %2, %0;" : "+l"(acc[i][4]) : "l"(aa), "l"(w4)); \
           } } }

    // ---------------- main sequential loop ----------------------------------
    for (int step = 0; step < STEPS; ++step) {

        ZERO_ACC()

        // ===== phase A (independent): h[s-25] 8 blocks, then x 4 blocks =====
        {
            const float* pH = g_hT + ((step - 25) & 31) * HB + kh1W * 64 + b_lo;
            // (h25 rows kh25W-512 = ks*32 = kh1W in h-col space)
            LOADBLK(bufA, pH, 0)
            #pragma unroll 1
            for (int blk = 0; blk < 8; blk += 2) {
                LOADBLK(bufB, pH, blk + 1)
                FMABLK(bufA, kh25W, blk)
                if (blk + 2 < 8) LOADBLK(bufA, pH, blk + 2)
                FMABLK(bufB, kh25W, blk + 1)
            }
        }
        {
            const float* pX = g_xT + (size_t)step * XB + (ks * 16) * 64 + b_lo;
            LOADBLK(bufA, pX, 0)
            LOADBLK(bufB, pX, 1)
            FMABLK(bufA, kxW, 0)
            LOADBLK(bufA, pX, 2)
            FMABLK(bufB, kxW, 1)
            LOADBLK(bufB, pX, 3)
            FMABLK(bufA, kxW, 2)
            FMABLK(bufB, kxW, 3)
        }

        // ===== per-warp wait (8 flags; steady state: already set) =====
        if (step > 0) warp_wait8(prodbase, lane, (unsigned)step);

        // ===== phase B: h[s-1] 8 blocks at full 4-warp/SMSP rate =====
        {
            const float* pH = g_hT + ((step - 1) & 31) * HB + kh1W * 64 + b_lo;
            LOADBLK(bufA, pH, 0)
            #pragma unroll 1
            for (int blk = 0; blk < 8; blk += 2) {
                LOADBLK(bufB, pH, blk + 1)
                FMABLK(bufA, kh1W, blk)
                if (blk + 2 < 8) LOADBLK(bufA, pH, blk + 2)
                FMABLK(bufB, kh1W, blk + 1)
            }
        }

        BAR1();   // gates(step-1) done reading red (warps 0-7 arrive post-gates)

        // ---- store partials ----
        {
            float* rrow = red + ks * RS + ng2;
            #pragma unroll
            for (int i = 0; i < 4; ++i) {
                int rb = (b_lo + i) * NPC;
                #pragma unroll
                for (int g = 0; g < 5; ++g)
                    *(float2*)(rrow + rb + g * 4) = *(float2*)&acc[i][g];
            }
        }

        BAR2();   // all partials visible

        if (ks < 8) {
            // ---- reduce 16 k-slices + gates (threads 0..255) ----
            float z[5];
            #pragma unroll
            for (int g = 0; g < 5; ++g) {
                float s = ba[g];
                const float* rp = red + bg * NPC + g * 4 + hcg;
                #pragma unroll
                for (int q = 0; q < KSL; ++q) s += rp[q * RS];
                z[g] = s;
            }
            float cs = c_s[((step + 24) % 25) * 256 + t];
            float ct = c_s[(step % 25) * 256 + t];
            float cc = fsig(z[0]) * ftanh(z[3]) + fsig(z[1]) * cs + fsig(z[2]) * ct;
            float hv = fsig(z[4]) * ftanh(cc);

            // publish-critical store FIRST
            int n = nt * 4 + hcg;
            g_hT[(step & 31) * HB + n * 64 + bg] = hv;

            BAR3();   // all 256 h stores done
            if (t == 0) {
                unsigned k1 = (unsigned)(step + 1);
                asm volatile("st.release.gpu.global.u32 [%0], %1;"
                             :: "l"(&g_flags[cta * 8]), "r"(k1) : "memory");
            }

            // off-critical-path stores AFTER publish
            c_s[(step % 25) * 256 + t] = cc;
            out[(size_t)step * BH + bg * Hh + n] = hv;
        }
        // warps 8-15: straight into step+1's independent phase A
    }
#undef ZERO_ACC
#undef LOADBLK
#undef FMABLK
}

// --------------------------- launch ----------------------------------------
extern "C" void kernel_launch(void* const* d_in, const int* in_sizes, int n_in,
                              void* d_out, int out_size)
{
    const float* x    = (const float*)d_in[0];
    const float* Wx   = (const float*)d_in[1];
    const float* Whs  = (const float*)d_in[2];
    const float* Wht  = (const float*)d_in[3];
    const float* bias = (const float*)d_in[4];
    float*       out  = (float*)d_out;

    cudaFuncSetAttribute(stlstm_kernel,
                         cudaFuncAttributeMaxDynamicSharedMemorySize, SMEM_BYTES);
    stlstm_kernel<<<NCTA, NTHR, SMEM_BYTES>>>(x, Wx, Whs, Wht, bias, out);
}

// round 14
// speedup vs baseline: 1.2633x; 1.0299x over previous
#include <cuda_runtime.h>
#include <cstdint>

// ---------------------------------------------------------------------------
// ST-LSTM persistent kernel, fp32 f32x2. Round 13 = R12 +
//  (a) red transposed to [ks][col20][b68]: STS.128 conflict-free (was 8-way)
//  (b) phase-A(s+1) block-0 prefetched BEFORE BAR2 (hides post-barrier L2 lat)
//  (c) first block uses mul.rn.f32x2 (no ZERO_ACC movs)
// Symmetric warps, dependency-ordered phases; per-warp 8-flag wait.
// 128 CTAs x 512 thr. CTA owns 4 h-cols (20 z-cols), full K=1280.
// ---------------------------------------------------------------------------

#define NCTA 128
#define NTHR 512

constexpr int Bb = 64, Ii = 256, Hh = 512;
constexpr int G5H   = 2560;
constexpr int STEPS = 1600;
constexpr int HB    = Hh * Bb;     // 32768
constexpr int XB    = Ii * Bb;     // 16384
constexpr int BH    = Bb * Hh;
constexpr int NPC   = 20;          // z-cols per CTA
constexpr int KSL   = 16;          // k-slices (= warps)
constexpr int BP    = 68;          // b-stride in red (64 + 4 pad)
constexpr int RS2   = NPC * BP;    // 1360 floats per k-slice

constexpr int W_OFF = 0;                    // 1280*20 = 25600
constexpr int R_OFF = 25600;                // 16*1360 = 21760
constexpr int C_OFF = R_OFF + KSL * RS2;    // 25*256  = 6400
constexpr int SM_FLOATS  = C_OFF + 25 * 256;           // 53760
constexpr int SMEM_BYTES = SM_FLOATS * 4;              // 215,040 B

// --------------------------- device scratch --------------------------------
__device__ float    g_xT[(size_t)STEPS * XB];  // x transposed [tj][i][b]
__device__ float    g_hT[32 * HB];             // h ring [slot][n][b]
__device__ unsigned g_flags[NCTA * 8];         // per-CTA published-step counters
__device__ unsigned g_cnt = 0;                 // init barrier (one-shot, self-reset)
__device__ unsigned g_gen = 0;

// --------------------------- helpers ---------------------------------------
__device__ __forceinline__ void init_barrier() {
    __syncthreads();
    if (threadIdx.x == 0) {
        unsigned gen = *(volatile unsigned*)&g_gen;
        __threadfence();
        unsigned rank = atomicAdd(&g_cnt, 1u);
        if (rank == NCTA - 1) {
            g_cnt = 0;
            __threadfence();
            *(volatile unsigned*)&g_gen = gen + 1u;
        } else {
            while (*(volatile unsigned*)&g_gen == gen) { __nanosleep(64); }
        }
        __threadfence();
    }
    __syncthreads();
}

// warp-scoped wait: lanes 0..7 poll this warp's 8 producer flags (acquire).
__device__ __forceinline__ void warp_wait8(int prodbase, int lane, unsigned k) {
    if (lane < 8) {
        const unsigned* p = &g_flags[(prodbase + lane) * 8];
        unsigned v;
        int spins = 0;
        for (;;) {
            asm volatile("ld.acquire.gpu.global.u32 %0, [%1];" : "=r"(v) : "l"(p));
            if ((int)(v - k) >= 0) break;
            if (++spins > 16) __nanosleep(32);
        }
    }
    __syncwarp();
}

#define BAR1() asm volatile("bar.sync 1, 512;" ::: "memory")
#define BAR2() asm volatile("bar.sync 2, 512;" ::: "memory")
#define BAR3() asm volatile("bar.sync 3, 256;" ::: "memory")

__device__ __forceinline__ float fexp(float x) {
    float r;
    asm("ex2.approx.f32 %0, %1;" : "=f"(r) : "f"(x * 1.4426950408889634f));
    return r;
}
__device__ __forceinline__ float frcp(float x) {
    float r;
    asm("rcp.approx.f32 %0, %1;" : "=f"(r) : "f"(x));
    return r;
}
__device__ __forceinline__ float fsig(float x)  { return frcp(1.0f + fexp(-x)); }
__device__ __forceinline__ float ftanh(float x) { return 1.0f - 2.0f * frcp(1.0f + fexp(2.0f * x)); }

// --------------------------- kernel ----------------------------------------
__global__ void __launch_bounds__(NTHR, 1)
stlstm_kernel(const float* __restrict__ x,
              const float* __restrict__ Wx,
              const float* __restrict__ Whs,
              const float* __restrict__ Wht,
              const float* __restrict__ bias,
              float* __restrict__ out)
{
    extern __shared__ float sm[];
    float* W_s = sm + W_OFF;
    float* red = sm + R_OFF;    // [16][20 cols][68 b]
    float* c_s = sm + C_OFF;

    const int t   = threadIdx.x;
    const int cta = blockIdx.x;
    const int nt  = cta;

    // -------- pre-barrier init: flags, x transpose, ring zero, weights ------
    if (t == 0) *(volatile unsigned*)&g_flags[cta * 8] = 0u;
    {
        float* tmp = red;                      // 21760 floats >= 64*257
        for (int tj = cta; tj < STEPS; tj += NCTA) {
            const float* xsrc = x + (size_t)tj * (Bb * Ii);
            for (int idx = t; idx < Bb * Ii; idx += NTHR) {
                int bb = idx >> 8, ii = idx & 255;
                tmp[bb * 257 + ii] = xsrc[idx];
            }
            __syncthreads();
            float* xdst = g_xT + (size_t)tj * XB;
            for (int idx = t; idx < Bb * Ii; idx += NTHR) {
                int ii = idx >> 6, bb = idx & 63;
                xdst[idx] = tmp[bb * 257 + ii];
            }
            __syncthreads();
        }
    }
    {   // zero h-ring slots 7..31 (all early reads land there)
        float* z = g_hT + 7 * HB;
        for (int idx = cta * NTHR + t; idx < 25 * HB; idx += NCTA * NTHR) z[idx] = 0.0f;
    }
    for (int idx = t; idx < 25 * 256; idx += NTHR) c_s[idx] = 0.0f;

    for (int idx = t; idx < 1280 * NPC; idx += NTHR) {
        int k = idx / NPC, c = idx % NPC;
        int g = c >> 2, hc = c & 3;
        int col = g * Hh + nt * 4 + hc;
        float w;
        if (k < Hh)            w = Whs[(size_t)k * G5H + col];
        else if (k < 2 * Hh)   w = Wht[(size_t)(k - Hh) * G5H + col];
        else                   w = Wx [(size_t)(k - 2 * Hh) * G5H + col];
        W_s[idx] = w;
    }

    float ba[5];
    {
        int hc = t & 3;
        #pragma unroll
        for (int g = 0; g < 5; ++g) ba[g] = bias[g * Hh + nt * 4 + hc];
    }

    init_barrier();   // x ready, rings zeroed, flags zeroed everywhere

    // GEMM mapping: thread = (ng, mg, ks); ks warp-uniform.
    const int ng    = t & 1;
    const int mg    = (t >> 1) & 15;
    const int ks    = t >> 5;
    const int lane  = t & 31;
    const int b_lo  = mg * 4;
    const int ng2   = ng * 2;
    const int kh1W  = ks * 32;           // W row base, h1 part
    const int kh25W = 512 + ks * 32;     // W row base, h25 part
    const int kxW   = 1024 + ks * 16;    // W row base, x part

    const int prodbase = ks * 8;         // 8 producer CTAs (h-cols ks*32..+31)

    const int bg  = t >> 2;              // gate phase (t < 256)
    const int hcg = t & 3;

    unsigned long long acc[4][5];
    float4 bufA[4], bufB[4];

#define LOADBLK(BUF, PA, BLK)                                                 \
    {  _Pragma("unroll")                                                      \
       for (int u = 0; u < 4; ++u)                                            \
           BUF[u] = __ldcg((const float4*)((PA) + ((BLK) * 4 + u) * 64));     \
    }

#define FMABLK(BUF, KWB, BLK)                                                 \
    {  _Pragma("unroll")                                                      \
       for (int u = 0; u < 4; ++u) {                                          \
           const float* wr = W_s + ((KWB) + (BLK) * 4 + u) * NPC + ng2;       \
           unsigned long long w0 = *(const unsigned long long*)(wr);          \
           unsigned long long w1 = *(const unsigned long long*)(wr + 4);      \
           unsigned long long w2 = *(const unsigned long long*)(wr + 8);      \
           unsigned long long w3 = *(const unsigned long long*)(wr + 12);     \
           unsigned long long w4 = *(const unsigned long long*)(wr + 16);     \
           float av[4] = {BUF[u].x, BUF[u].y, BUF[u].z, BUF[u].w};            \
           _Pragma("unroll")                                                  \
           for (int i = 0; i < 4; ++i) {                                      \
               unsigned long long aa;                                         \
               asm("mov.b64 %0, {%1, %1};" : "=l"(aa) : "f"(av[i]));          \
               asm("fma.rn.f32x2 %0, %1, %2, %0;" : "+l"(acc[i][0]) : "l"(aa), "l"(w0)); \
               asm("fma.rn.f32x2 %0, %1, %2, %0;" : "+l"(acc[i][1]) : "l"(aa), "l"(w1)); \
               asm("fma.rn.f32x2 %0, %1, %2, %0;" : "+l"(acc[i][2]) : "l"(aa), "l"(w2)); \
               asm("fma.rn.f32x2 %0, %1, %2, %0;" : "+l"(acc[i][3]) : "l"(aa), "l"(w3)); \
               asm("fma.rn.f32x2 %0, %1, %2, %0;" : "+l"(acc[i][4]) : "l"(aa), "l"(w4)); \
           } } }

    // first block of the step: acc = a*w (no pre-zero needed)
#define MULBLK(BUF, KWB, BLK)                                                 \
    {  _Pragma("unroll")                                                      \
       for (int u = 0; u < 4; ++u) {                                          \
           const float* wr = W_s + ((KWB) + (BLK) * 4 + u) * NPC + ng2;       \
           unsigned long long w0 = *(const unsigned long long*)(wr);          \
           unsigned long long w1 = *(const unsigned long long*)(wr + 4);      \
           unsigned long long w2 = *(const unsigned long long*)(wr + 8);      \
           unsigned long long w3 = *(const unsigned long long*)(wr + 12);     \
           unsigned long long w4 = *(const unsigned long long*)(wr + 16);     \
           float av[4] = {BUF[u].x, BUF[u].y, BUF[u].z, BUF[u].w};            \
           _Pragma("unroll")                                                  \
           for (int i = 0; i < 4; ++i) {                                      \
               unsigned long long aa;                                         \
               asm("mov.b64 %0, {%1, %1};" : "=l"(aa) : "f"(av[i]));          \
               if (u == 0) {                                                  \
                   asm("mul.rn.f32x2 %0, %1, %2;" : "=l"(acc[i][0]) : "l"(aa), "l"(w0)); \
                   asm("mul.rn.f32x2 %0, %1, %2;" : "=l"(acc[i][1]) : "l"(aa), "l"(w1)); \
                   asm("mul.rn.f32x2 %0, %1, %2;" : "=l"(acc[i][2]) : "l"(aa), "l"(w2)); \
                   asm("mul.rn.f32x2 %0, %1, %2;" : "=l"(acc[i][3]) : "l"(aa), "l"(w3)); \
                   asm("mul.rn.f32x2 %0, %1, %2;" : "=l"(acc[i][4]) : "l"(aa), "l"(w4)); \
               } else {                                                       \
                   asm("fma.rn.f32x2 %0, %1, %2, %0;" : "+l"(acc[i][0]) : "l"(aa), "l"(w0)); \
                   asm("fma.rn.f32x2 %0, %1, %2, %0;" : "+l"(acc[i][1]) : "l"(aa), "l"(w1)); \
                   asm("fma.rn.f32x2 %0, %1, %2, %0;" : "+l"(acc[i][2]) : "l"(aa), "l"(w2)); \
                   asm("fma.rn.f32x2 %0, %1, %2, %0;" : "+l"(acc[i][3]) : "l"(aa), "l"(w3)); \
                   asm("fma.rn.f32x2 %0, %1, %2, %0;" : "+l"(acc[i][4]) : "l"(aa), "l"(w4)); \
               } } } }

    // prologue: prefetch phase-A block 0 of step 0 (slot 7 zeroed)
    {
        const float* pH0 = g_hT + ((0 - 25) & 31) * HB + kh1W * 64 + b_lo;
        LOADBLK(bufA, pH0, 0)
    }

    // ---------------- main sequential loop ----------------------------------
    for (int step = 0; step < STEPS; ++step) {

        // ===== phase A (independent): h[s-25] 8 blocks (block 0 prefetched),
        //       then x 4 blocks =====
        {
            const float* pH = g_hT + ((step - 25) & 31) * HB + kh1W * 64 + b_lo;
            LOADBLK(bufB, pH, 1)
            MULBLK(bufA, kh25W, 0)
            #pragma unroll 1
            for (int blk = 1; blk < 7; blk += 2) {
                LOADBLK(bufA, pH, blk + 1)
                FMABLK(bufB, kh25W, blk)
                LOADBLK(bufB, pH, blk + 2)
                FMABLK(bufA, kh25W, blk + 1)
            }
            FMABLK(bufB, kh25W, 7)
        }
        {
            const float* pX = g_xT + (size_t)step * XB + (ks * 16) * 64 + b_lo;
            LOADBLK(bufA, pX, 0)
            LOADBLK(bufB, pX, 1)
            FMABLK(bufA, kxW, 0)
            LOADBLK(bufA, pX, 2)
            FMABLK(bufB, kxW, 1)
            LOADBLK(bufB, pX, 3)
            FMABLK(bufA, kxW, 2)
            FMABLK(bufB, kxW, 3)
        }

        // ===== per-warp wait (8 flags; steady state: already set) =====
        if (step > 0) warp_wait8(prodbase, lane, (unsigned)step);

        // ===== phase B: h[s-1] 8 blocks at full 4-warp/SMSP rate =====
        {
            const float* pH = g_hT + ((step - 1) & 31) * HB + kh1W * 64 + b_lo;
            LOADBLK(bufA, pH, 0)
            #pragma unroll 1
            for (int blk = 0; blk < 8; blk += 2) {
                LOADBLK(bufB, pH, blk + 1)
                FMABLK(bufA, kh1W, blk)
                if (blk + 2 < 8) LOADBLK(bufA, pH, blk + 2)
                FMABLK(bufB, kh1W, blk + 1)
            }
        }

        BAR1();   // gates(step-1) done reading red (warps 0-7 arrive post-gates)

        // ---- store partials: [ks][col][b] layout, STS.128, conflict-free ----
        {
            float* rk = red + ks * RS2 + b_lo;
            #pragma unroll
            for (int g = 0; g < 5; ++g) {
                const float2* a0 = (const float2*)&acc[0][g];
                const float2* a1 = (const float2*)&acc[1][g];
                const float2* a2 = (const float2*)&acc[2][g];
                const float2* a3 = (const float2*)&acc[3][g];
                *(float4*)(rk + (g * 4 + ng2 + 0) * BP) =
                    make_float4(a0->x, a1->x, a2->x, a3->x);
                *(float4*)(rk + (g * 4 + ng2 + 1) * BP) =
                    make_float4(a0->y, a1->y, a2->y, a3->y);
            }
        }

        // ---- prefetch phase-A(s+1) block 0 BEFORE the barrier ----
        {
            const float* pHn = g_hT + ((step - 24) & 31) * HB + kh1W * 64 + b_lo;
            LOADBLK(bufA, pHn, 0)
        }

        BAR2();   // all partials visible

        if (ks < 8) {
            // ---- reduce 16 k-slices + gates (threads 0..255) ----
            float z[5];
            #pragma unroll
            for (int g = 0; g < 5; ++g) {
                float s = ba[g];
                const float* rp = red + (g * 4 + hcg) * BP + bg;
                #pragma unroll
                for (int q = 0; q < KSL; ++q) s += rp[q * RS2];
                z[g] = s;
            }
            float cs = c_s[((step + 24) % 25) * 256 + t];
            float ct = c_s[(step % 25) * 256 + t];
            float cc = fsig(z[0]) * ftanh(z[3]) + fsig(z[1]) * cs + fsig(z[2]) * ct;
            float hv = fsig(z[4]) * ftanh(cc);

            // publish-critical store FIRST
            int n = nt * 4 + hcg;
            g_hT[(step & 31) * HB + n * 64 + bg] = hv;

            BAR3();   // all 256 h stores done
            if (t == 0) {
                unsigned k1 = (unsigned)(step + 1);
                asm volatile("st.release.gpu.global.u32 [%0], %1;"
                             :: "l"(&g_flags[cta * 8]), "r"(k1) : "memory");
            }

            // off-critical-path stores AFTER publish
            c_s[(step % 25) * 256 + t] = cc;
            out[(size_t)step * BH + bg * Hh + n] = hv;
        }
        // warps 8-15: straight into step+1's phase A (bufA already in flight)
    }
#undef LOADBLK
#undef FMABLK
#undef MULBLK
}

// --------------------------- launch ----------------------------------------
extern "C" void kernel_launch(void* const* d_in, const int* in_sizes, int n_in,
                              void* d_out, int out_size)
{
    const float* x    = (const float*)d_in[0];
    const float* Wx   = (const float*)d_in[1];
    const float* Whs  = (const float*)d_in[2];
    const float* Wht  = (const float*)d_in[3];
    const float* bias = (const float*)d_in[4];
    float*       out  = (float*)d_out;

    cudaFuncSetAttribute(stlstm_kernel,
                         cudaFuncAttributeMaxDynamicSharedMemorySize, SMEM_BYTES);
    stlstm_kernel<<<NCTA, NTHR, SMEM_BYTES>>>(x, Wx, Whs, Wht, bias, out);
}